// round 1
// baseline (speedup 1.0000x reference)
#include <cuda_runtime.h>
#include <math.h>

#define NUM_B 2
#define NUM_C 256
#define NUM_H 256
#define NUM_W 256
#define NUM_N 512
#define OUT_H 7
#define OUT_W 7
#define NBIN 49
#define HW (NUM_H * NUM_W)
#define CHW (NUM_C * HW)

__global__ __launch_bounds__(256) void rroi_pool_kernel(
    const float* __restrict__ x,
    const float* __restrict__ boxes,
    float* __restrict__ out)
{
    __shared__ int4   s_off[NBIN];   // spatial offsets (y*W+x) for lt, rt, rb, lb
    __shared__ float4 s_w[NBIN];     // weights (validity folded in) for lt, rt, rb, lb

    const int roi = blockIdx.x;
    const int tid = threadIdx.x;

    if (tid < NBIN) {
        const float* bx = boxes + roi * 5;
        // Replicate reference fp32 arithmetic (no fma contraction).
        float cx  = __fmul_rn(bx[0], 0.25f);
        float cy  = __fmul_rn(bx[1], 0.25f);
        float w   = __fmul_rn(bx[2], 0.25f);
        float h   = __fmul_rn(bx[3], 0.25f);
        float ang = __fmul_rn(bx[4], 0.017453292519943295f);  // pi/180 (fp32)

        float Sx = __fdiv_rn(w, 7.0f);
        float Sy = __fdiv_rn(h, 7.0f);
        float ca = cosf(ang);
        float sa = sinf(ang);

        const float dxc = -3.5f;  // -OUT_W/2
        const float dyc = -3.5f;  // -OUT_H/2

        float M00 = __fmul_rn(ca, Sx);
        float M01 = __fmul_rn(sa, Sy);
        float M02 = __fadd_rn(__fadd_rn(__fmul_rn(__fmul_rn(ca, Sx), dxc),
                                        __fmul_rn(__fmul_rn(sa, Sy), dyc)), cx);
        float M10 = __fmul_rn(-sa, Sx);
        float M11 = __fmul_rn(ca, Sy);
        float M12 = __fadd_rn(__fadd_rn(__fmul_rn(__fmul_rn(-sa, Sx), dxc),
                                        __fmul_rn(__fmul_rn(ca, Sy), dyc)), cy);

        int ph = tid / OUT_W;
        int pw = tid - ph * OUT_W;

        // 4 corners: offs = {(0,0),(0,1),(1,0),(1,1)} applied as (pw+o0, ph+o1)
        const float offx[4] = {0.f, 0.f, 1.f, 1.f};
        const float offy[4] = {0.f, 1.f, 0.f, 1.f};

        float minX =  3.0e38f, maxX = -3.0e38f;
        float minY =  3.0e38f, maxY = -3.0e38f;
        #pragma unroll
        for (int k = 0; k < 4; ++k) {
            float pwc = (float)pw + offx[k];
            float phc = (float)ph + offy[k];
            float X = __fadd_rn(__fadd_rn(__fmul_rn(M00, pwc), __fmul_rn(M01, phc)), M02);
            float Y = __fadd_rn(__fadd_rn(__fmul_rn(M10, pwc), __fmul_rn(M11, phc)), M12);
            minX = fminf(minX, X); maxX = fmaxf(maxX, X);
            minY = fminf(minY, Y); maxY = fmaxf(maxY, Y);
        }

        // rintf = round-half-even, same as jnp.round
        float lM = fmaxf(rintf(minX), 0.0f);
        float rM = fminf(rintf(maxX), (float)(NUM_W - 1));
        float tM = fmaxf(rintf(minY), 0.0f);
        float bM = fminf(rintf(maxY), (float)(NUM_H - 1));

        float bcx = __fmul_rn(__fadd_rn(lM, rM), 0.5f);
        float bcy = __fmul_rn(__fadd_rn(tM, bM), 0.5f);

        float flx = floorf(bcx);
        float fly = floorf(bcy);
        int il = (int)flx;
        int it = (int)fly;
        int ir = (int)ceilf(bcx);
        int ib = (int)ceilf(bcy);
        float rx = __fsub_rn(bcx, flx);
        float ry = __fsub_rn(bcy, fly);

        float omrx = __fsub_rn(1.0f, rx);
        float omry = __fsub_rn(1.0f, ry);
        float wlt = __fmul_rn(omrx, omry);
        float wrt = __fmul_rn(rx,   omry);
        float wrb = __fmul_rn(rx,   ry);
        float wlb = __fmul_rn(omrx, ry);

        bool vl = (il >= 0) && (il < NUM_W);
        bool vr = (ir >= 0) && (ir < NUM_W);
        bool vt = (it >= 0) && (it < NUM_H);
        bool vb = (ib >= 0) && (ib < NUM_H);

        int cl = min(max(il, 0), NUM_W - 1);
        int cr = min(max(ir, 0), NUM_W - 1);
        int ct = min(max(it, 0), NUM_H - 1);
        int cb = min(max(ib, 0), NUM_H - 1);

        int4 o;
        o.x = ct * NUM_W + cl;   // lt
        o.y = ct * NUM_W + cr;   // rt
        o.z = cb * NUM_W + cr;   // rb
        o.w = cb * NUM_W + cl;   // lb
        s_off[tid] = o;

        float4 wv;
        wv.x = (vt && vl) ? wlt : 0.0f;
        wv.y = (vt && vr) ? wrt : 0.0f;
        wv.z = (vb && vr) ? wrb : 0.0f;
        wv.w = (vb && vl) ? wlb : 0.0f;
        s_w[tid] = wv;
    }
    __syncthreads();

    const float* fb = x + (size_t)(roi >> 9) * CHW;   // roi/512 = batch
    float* ob = out + (size_t)roi * (NUM_C * NBIN);

    int c   = tid / NBIN;        // 0..5
    int bin = tid - c * NBIN;

    // 256*49 = 12544 elements, 256 threads -> exactly 49 iterations each
    for (int i = 0; i < 49; ++i) {
        int idx = tid + (i << 8);
        const float* pc = fb + c * HW;
        int4   o  = s_off[bin];
        float4 wv = s_w[bin];
        // Sum order matches reference: lt*wlt + rt*wrt + rb*wrb + lb*wlb
        float v = pc[o.x] * wv.x + pc[o.y] * wv.y + pc[o.z] * wv.z + pc[o.w] * wv.w;
        ob[idx] = fmaxf(v, 0.0f);

        // idx += 256  ==  c += 5, bin += 11 (with carry)
        bin += 11;
        c   += 5;
        if (bin >= NBIN) { bin -= NBIN; c += 1; }
    }
}

extern "C" void kernel_launch(void* const* d_in, const int* in_sizes, int n_in,
                              void* d_out, int out_size) {
    const float* x     = (const float*)d_in[0];   // (2,256,256,256) f32
    const float* boxes = (const float*)d_in[1];   // (2,512,5) f32
    float* out = (float*)d_out;                   // (1024,256,7,7) f32
    (void)in_sizes; (void)n_in; (void)out_size;

    rroi_pool_kernel<<<NUM_B * NUM_N, 256>>>(x, boxes, out);
}

// round 2
// speedup vs baseline: 1.3244x; 1.3244x over previous
#include <cuda_runtime.h>
#include <math.h>

#define NUM_B 2
#define NUM_C 256
#define NUM_H 256
#define NUM_W 256
#define NUM_N 512
#define OUT_H 7
#define OUT_W 7
#define NBIN 49
#define HW (NUM_H * NUM_W)
#define CHW (NUM_C * HW)
#define C_HALF 128

__global__ __launch_bounds__(256) void rroi_pool_kernel(
    const float* __restrict__ x,
    const float* __restrict__ boxes,
    float* __restrict__ out)
{
    __shared__ int4   s_off[NBIN];   // spatial offsets (y*W+x) for lt, rt, rb, lb
    __shared__ float4 s_w[NBIN];     // weights (validity folded in)

    const int roi  = blockIdx.x >> 1;
    const int half = blockIdx.x & 1;
    const int tid  = threadIdx.x;

    if (tid < NBIN) {
        const float* bx = boxes + roi * 5;
        float cx  = __fmul_rn(bx[0], 0.25f);
        float cy  = __fmul_rn(bx[1], 0.25f);
        float w   = __fmul_rn(bx[2], 0.25f);
        float h   = __fmul_rn(bx[3], 0.25f);
        float ang = __fmul_rn(bx[4], 0.017453292519943295f);

        float Sx = __fdiv_rn(w, 7.0f);
        float Sy = __fdiv_rn(h, 7.0f);
        float ca = cosf(ang);
        float sa = sinf(ang);

        const float dxc = -3.5f;
        const float dyc = -3.5f;

        float M00 = __fmul_rn(ca, Sx);
        float M01 = __fmul_rn(sa, Sy);
        float M02 = __fadd_rn(__fadd_rn(__fmul_rn(__fmul_rn(ca, Sx), dxc),
                                        __fmul_rn(__fmul_rn(sa, Sy), dyc)), cx);
        float M10 = __fmul_rn(-sa, Sx);
        float M11 = __fmul_rn(ca, Sy);
        float M12 = __fadd_rn(__fadd_rn(__fmul_rn(__fmul_rn(-sa, Sx), dxc),
                                        __fmul_rn(__fmul_rn(ca, Sy), dyc)), cy);

        int ph = tid / OUT_W;
        int pw = tid - ph * OUT_W;

        const float offx[4] = {0.f, 0.f, 1.f, 1.f};
        const float offy[4] = {0.f, 1.f, 0.f, 1.f};

        float minX =  3.0e38f, maxX = -3.0e38f;
        float minY =  3.0e38f, maxY = -3.0e38f;
        #pragma unroll
        for (int k = 0; k < 4; ++k) {
            float pwc = (float)pw + offx[k];
            float phc = (float)ph + offy[k];
            float X = __fadd_rn(__fadd_rn(__fmul_rn(M00, pwc), __fmul_rn(M01, phc)), M02);
            float Y = __fadd_rn(__fadd_rn(__fmul_rn(M10, pwc), __fmul_rn(M11, phc)), M12);
            minX = fminf(minX, X); maxX = fmaxf(maxX, X);
            minY = fminf(minY, Y); maxY = fmaxf(maxY, Y);
        }

        float lM = fmaxf(rintf(minX), 0.0f);
        float rM = fminf(rintf(maxX), (float)(NUM_W - 1));
        float tM = fmaxf(rintf(minY), 0.0f);
        float bM = fminf(rintf(maxY), (float)(NUM_H - 1));

        float bcx = __fmul_rn(__fadd_rn(lM, rM), 0.5f);
        float bcy = __fmul_rn(__fadd_rn(tM, bM), 0.5f);

        float flx = floorf(bcx);
        float fly = floorf(bcy);
        int il = (int)flx;
        int it = (int)fly;
        int ir = (int)ceilf(bcx);
        int ib = (int)ceilf(bcy);
        float rx = __fsub_rn(bcx, flx);
        float ry = __fsub_rn(bcy, fly);

        float omrx = __fsub_rn(1.0f, rx);
        float omry = __fsub_rn(1.0f, ry);
        float wlt = __fmul_rn(omrx, omry);
        float wrt = __fmul_rn(rx,   omry);
        float wrb = __fmul_rn(rx,   ry);
        float wlb = __fmul_rn(omrx, ry);

        bool vl = (il >= 0) && (il < NUM_W);
        bool vr = (ir >= 0) && (ir < NUM_W);
        bool vt = (it >= 0) && (it < NUM_H);
        bool vb = (ib >= 0) && (ib < NUM_H);

        int cl = min(max(il, 0), NUM_W - 1);
        int cr = min(max(ir, 0), NUM_W - 1);
        int ct = min(max(it, 0), NUM_H - 1);
        int cb = min(max(ib, 0), NUM_H - 1);

        int4 o;
        o.x = ct * NUM_W + cl;   // lt
        o.y = ct * NUM_W + cr;   // rt
        o.z = cb * NUM_W + cr;   // rb
        o.w = cb * NUM_W + cl;   // lb
        s_off[tid] = o;

        float4 wv;
        wv.x = (vt && vl) ? wlt : 0.0f;
        wv.y = (vt && vr) ? wrt : 0.0f;
        wv.z = (vb && vr) ? wrb : 0.0f;
        wv.w = (vb && vl) ? wlb : 0.0f;
        s_w[tid] = wv;
    }
    __syncthreads();

    if (tid >= 5 * NBIN) return;   // 245 active threads

    const int bin = tid % NBIN;
    const int c0  = tid / NBIN;    // 0..4

    // Offsets & weights in registers; loop is pure gather+fma+store.
    const int4   o  = s_off[bin];
    const float4 wv = s_w[bin];

    const float* fb = x + (size_t)(roi >> 9) * CHW;
    float* ob = out + (size_t)roi * (NUM_C * NBIN) + bin;

    const int cbeg = half * C_HALF + c0;
    const int cend = half * C_HALF + C_HALF;

    #pragma unroll 4
    for (int c = cbeg; c < cend; c += 5) {
        const float* pc = fb + (size_t)c * HW;
        float v = pc[o.x] * wv.x + pc[o.y] * wv.y + pc[o.z] * wv.z + pc[o.w] * wv.w;
        ob[(size_t)c * NBIN] = fmaxf(v, 0.0f);
    }
}

extern "C" void kernel_launch(void* const* d_in, const int* in_sizes, int n_in,
                              void* d_out, int out_size) {
    const float* x     = (const float*)d_in[0];   // (2,256,256,256) f32
    const float* boxes = (const float*)d_in[1];   // (2,512,5) f32
    float* out = (float*)d_out;                   // (1024,256,7,7) f32
    (void)in_sizes; (void)n_in; (void)out_size;

    rroi_pool_kernel<<<NUM_B * NUM_N * 2, 256>>>(x, boxes, out);
}